// round 13
// baseline (speedup 1.0000x reference)
#include <cuda_runtime.h>
#include <cstdint>

#define FEAT      256
#define PRE_CAP   16384
#define JT        16
#define JCH       (PRE_CAP / JT)
#define DEF_INSERT 999000
#define HB        1954                // hash blocks
#define HT        (HB * 256)          // 500224 threads, 2 slots each (>= 1e6)

typedef unsigned long long u64;

// ---------------- device scratch (no allocations allowed; zero-init) ----------------
__device__ u64      g_pre[PRE_CAP];        // ((0x7FFFFF - r) << 32) | index
__device__ int      g_npre;                // K1 atomic counter; reset by K3 (never read there)
__device__ int      g_npre2;               // snapshot written by K2, read by K3
__device__ int      g_rankp[JT][PRE_CAP];  // partial rank counts per j-tile

// ---------------- pipe-balanced add: IMAD on the fma pipe (one==1 at runtime) ----------------
__device__ __forceinline__ uint32_t addf(uint32_t a, uint32_t one, uint32_t b) {
    uint32_t r;
    asm("mad.lo.u32 %0, %1, %2, %3;" : "=r"(r) : "r"(a), "r"(one), "r"(b));
    return r;
}

__device__ __forceinline__ uint32_t rotl32(uint32_t x, int d) {
    return __funnelshift_l(x, x, d);    // SHF -> alu pipe
}

// ---------------- Threefry-2x32, 20 rounds, partitionable layout (JAX-exact) ----------------
__device__ __forceinline__ uint32_t jax_bits32(uint32_t j, uint32_t one) {
    const uint32_t k0 = 0u, k1 = 42u;
    const uint32_t ks2 = k0 ^ k1 ^ 0x1BD11BDAu;
    uint32_t x0 = k0, x1 = addf(j, one, k1);
#define TF_R(r) { x0 = addf(x0, one, x1); x1 = rotl32(x1, (r)); x1 ^= x0; }
    TF_R(13) TF_R(15) TF_R(26) TF_R(6)
    x0 = addf(x0, one, k1);  x1 = addf(x1, one, ks2 + 1u);
    TF_R(17) TF_R(29) TF_R(16) TF_R(24)
    x0 = addf(x0, one, ks2); x1 = addf(x1, one, k0 + 2u);
    TF_R(13) TF_R(15) TF_R(26) TF_R(6)
    x0 = addf(x0, one, k0);  x1 = addf(x1, one, k1 + 3u);
    TF_R(17) TF_R(29) TF_R(16) TF_R(24)
    x0 = addf(x0, one, k1);  x1 = addf(x1, one, ks2 + 4u);
    TF_R(13) TF_R(15) TF_R(26) TF_R(6)
    x0 = addf(x0, one, ks2); x1 = addf(x1, one, k0 + 5u);
#undef TF_R
    return x0 ^ x1;   // XOR-fold (jax_threefry_partitionable)
}

__device__ __forceinline__ int read_scalar(const int* p, int defv) {
    return p ? p[0] : defv;
}

__device__ __forceinline__ void warp_push(bool push, uint32_t r, int j, int lane) {
    unsigned mask = __ballot_sync(0xFFFFFFFFu, push);
    if (mask) {
        int leader = __ffs(mask) - 1;
        int base = 0;
        if (lane == leader) base = atomicAdd(&g_npre, __popc(mask));
        base = __shfl_sync(0xFFFFFFFFu, base, leader);
        if (push) {
            int pos = base + __popc(mask & ((1u << lane) - 1u));
            if (pos < PRE_CAP)
                g_pre[pos] = ((u64)(0x7FFFFFu - r) << 32) | (uint32_t)j;
        }
    }
}

// ---------------- K1: hash all slots, exactly 2 per thread, no loop ----------------
__global__ void __launch_bounds__(256)
k_hash_push(const int* __restrict__ d_size, int max_size, int data_len, int nsamp) {
    int new_size = read_scalar(d_size, max_size) + data_len;
    if (new_size > max_size) new_size = max_size;
    if (new_size < 0) new_size = 0;

    // keep top ~1.125*nsamp expected survivors (margin ~7.5 sigma)
    uint32_t precut = 0u;
    if (new_size > 0) {
        float keep_f = ((float)nsamp * 1.125f) * 8388608.0f / (float)new_size;
        u64 keep = (u64)keep_f;
        precut = (keep >= 0x800000ull) ? 0u : (uint32_t)(0x800000ull - keep);
    }

    const uint32_t one = blockDim.x >> 8;   // == 1, opaque to the compiler
    const int lane = threadIdx.x & 31;
    const int j0 = blockIdx.x * 256 + threadIdx.x;
    const int j1 = j0 + HT;

    uint32_t r0 = 0u, r1 = 0u;
    bool p0 = false, p1 = false;
    if (j0 < new_size) { r0 = jax_bits32((uint32_t)j0, one) >> 9; p0 = (r0 >= precut); }
    if (j1 < new_size) { r1 = jax_bits32((uint32_t)j1, one) >> 9; p1 = (r1 >= precut); }
    warp_push(p0, r0, j0, lane);
    warp_push(p1, r1, j1, lane);
}

// ---------------- K2: tiled exact rank + counter snapshot ----------------
__global__ void k_rank() {
    int npre = g_npre;
    if (npre > PRE_CAP) npre = PRE_CAP;

    if (blockIdx.x == 0 && blockIdx.y == 0 && threadIdx.x == 0)
        g_npre2 = npre;   // snapshot for K3; K2->K3 stream ordering

    if ((int)(blockIdx.x * blockDim.x) >= npre) return;   // uniform per block

    __shared__ u64 sk[JCH];
    int chunk = (npre + JT - 1) / JT;
    int j0 = blockIdx.y * chunk;
    int j1 = j0 + chunk; if (j1 > npre) j1 = npre;
    if (j0 >= npre) return;
    for (int j = j0 + threadIdx.x; j < j1; j += blockDim.x)
        sk[j - j0] = g_pre[j];
    __syncthreads();

    int t = blockIdx.x * blockDim.x + threadIdx.x;
    u64 mykey = (t < npre) ? g_pre[t] : ~0ull;
    int len = j1 - j0;
    int cnt = 0, j = 0;
    for (; j + 4 <= len; j += 4) {
        cnt += (sk[j]     < mykey);
        cnt += (sk[j + 1] < mykey);
        cnt += (sk[j + 2] < mykey);
        cnt += (sk[j + 3] < mykey);
    }
    for (; j < len; ++j) cnt += (sk[j] < mykey);
    if (t < npre) g_rankp[blockIdx.y][t] = cnt;
}

// ---------------- K3: fused finalize + gather, 2 candidates per warp (MLP=4) ----------------
__global__ void __launch_bounds__(256)
k_rank_gather(const float* __restrict__ buf, const float* __restrict__ tr,
              const int* __restrict__ d_ins, float* __restrict__ out,
              int max_size, int data_len, int nsamp) {
    // reset K1's counter for the next run/replay; no thread here reads g_npre
    if (blockIdx.x == 0 && threadIdx.x == 0) g_npre = 0;

    int npre = g_npre2;
    if (npre > PRE_CAP) npre = PRE_CAP;

    const int lane   = threadIdx.x & 31;
    const int warp   = (blockIdx.x * blockDim.x + threadIdx.x) >> 5;
    const int nwarps = (gridDim.x * blockDim.x) >> 5;
    const long p_ins = (long)(read_scalar(d_ins, DEF_INSERT) % max_size);

    for (int t0 = warp; t0 < npre; t0 += 2 * nwarps) {
        int t1 = t0 + nwarps;
        bool has1 = (t1 < npre);

        // both candidates' 16 partials packed into one REDUX (halves < 2^16)
        uint32_t part = 0u;
        if (lane < JT) {
            part = (uint32_t)g_rankp[lane][t0];
            if (has1) part |= ((uint32_t)g_rankp[lane][t1]) << 16;
        }
        uint32_t ranks = __reduce_add_sync(0xFFFFFFFFu, part);
        int rank0 = (int)(ranks & 0xFFFFu);
        int rank1 = (int)(ranks >> 16);

        bool do0 = (rank0 < nsamp);
        bool do1 = has1 && (rank1 < nsamp);

        const float4 *src0 = nullptr, *src1 = nullptr;
        if (do0) {
            uint32_t idx = (uint32_t)g_pre[t0];
            long off = (long)idx - p_ins; if (off < 0) off += max_size;
            src0 = (off < (long)data_len)
                ? (const float4*)(tr + (size_t)off * FEAT)
                : (const float4*)(buf + (size_t)idx * FEAT);
        }
        if (do1) {
            uint32_t idx = (uint32_t)g_pre[t1];
            long off = (long)idx - p_ins; if (off < 0) off += max_size;
            src1 = (off < (long)data_len)
                ? (const float4*)(tr + (size_t)off * FEAT)
                : (const float4*)(buf + (size_t)idx * FEAT);
        }

        float4 a0, a1, b0, b1;
        if (do0) { a0 = src0[lane]; a1 = src0[lane + 32]; }   // 4 loads in flight
        if (do1) { b0 = src1[lane]; b1 = src1[lane + 32]; }
        if (do0) {
            float4* dst = (float4*)(out + (size_t)rank0 * FEAT);
            dst[lane] = a0; dst[lane + 32] = a1;
        }
        if (do1) {
            float4* dst = (float4*)(out + (size_t)rank1 * FEAT);
            dst[lane] = b0; dst[lane + 32] = b1;
        }
    }
}

// ---------------- launcher ----------------
extern "C" void kernel_launch(void* const* d_in, const int* in_sizes, int n_in,
                              void* d_out, int out_size) {
    // Classify inputs by element count (robust to ordering):
    int i_buf = -1, i_tr = -1;
    int sc[3] = { -1, -1, -1 };
    int nsc = 0;
    for (int i = 0; i < n_in; ++i) {
        if (in_sizes[i] > 100000000)      i_buf = i;
        else if (in_sizes[i] > 1000000)   i_tr  = i;
        else if (in_sizes[i] >= 1 && in_sizes[i] <= 4 && nsc < 3) sc[nsc++] = i;
    }
    if (i_buf < 0) i_buf = 0;
    if (i_tr  < 0) i_tr  = 1;

    const float* buf   = (const float*)d_in[i_buf];
    const float* tr    = (const float*)d_in[i_tr];
    const int*   d_ins = (sc[0] >= 0) ? (const int*)d_in[sc[0]] : nullptr;
    const int*   d_sz  = (sc[1] >= 0) ? (const int*)d_in[sc[1]] : nullptr;

    int max_size = in_sizes[i_buf] / FEAT;   // 1,000,000
    int data_len = in_sizes[i_tr]  / FEAT;   // 16,384
    int nsamp    = out_size        / FEAT;   // 4,096

    k_hash_push<<<HB, 256>>>(d_sz, max_size, data_len, nsamp);
    dim3 rgrid(PRE_CAP / 256, JT);           // (64, 16)
    k_rank<<<rgrid, 256>>>();
    k_rank_gather<<<288, 256>>>(buf, tr, d_ins, (float*)d_out,
                                max_size, data_len, nsamp);   // 2304 warps, 2 cand each
}

// round 15
// speedup vs baseline: 1.0843x; 1.0843x over previous
#include <cuda_runtime.h>
#include <cstdint>

#define FEAT      256
#define PRE_CAP   16384
#define JT        16
#define JCH       (PRE_CAP / JT)
#define DEF_INSERT 999000
#define HB        2368                // hash blocks: exactly 2 waves (148 SMs * 8 CTAs * 2)
#define HT        (HB * 256)          // 606208; chain0 j<HT, chain1 j+HT (<1e6 only for early blocks)

typedef unsigned long long u64;

// ---------------- device scratch (no allocations allowed; zero-init) ----------------
__device__ u64      g_pre[PRE_CAP];        // ((0x7FFFFF - r) << 32) | index
__device__ int      g_npre;                // K1 atomic counter; reset by K3 (never read there)
__device__ int      g_npre2;               // snapshot written by K2, read by K3
__device__ int      g_rankp[JT][PRE_CAP];  // partial rank counts per j-tile

// ---------------- Threefry-2x32, 20 rounds, partitionable layout (JAX-exact) ----------------
__device__ __forceinline__ uint32_t rotl32(uint32_t x, int d) {
    return __funnelshift_l(x, x, d);
}

__device__ __forceinline__ uint32_t jax_bits32(uint32_t j) {
    const uint32_t k0 = 0u, k1 = 42u;
    const uint32_t ks2 = k0 ^ k1 ^ 0x1BD11BDAu;
    uint32_t x0 = 0u + k0, x1 = j + k1;
#define TF_R(r) { x0 += x1; x1 = rotl32(x1, (r)); x1 ^= x0; }
    TF_R(13) TF_R(15) TF_R(26) TF_R(6)   x0 += k1;  x1 += ks2 + 1u;
    TF_R(17) TF_R(29) TF_R(16) TF_R(24)  x0 += ks2; x1 += k0  + 2u;
    TF_R(13) TF_R(15) TF_R(26) TF_R(6)   x0 += k0;  x1 += k1  + 3u;
    TF_R(17) TF_R(29) TF_R(16) TF_R(24)  x0 += k1;  x1 += ks2 + 4u;
    TF_R(13) TF_R(15) TF_R(26) TF_R(6)   x0 += ks2; x1 += k0  + 5u;
#undef TF_R
    return x0 ^ x1;   // XOR-fold (jax_threefry_partitionable)
}

__device__ __forceinline__ int read_scalar(const int* p, int defv) {
    return p ? p[0] : defv;
}

__device__ __forceinline__ void warp_push(bool push, uint32_t r, int j, int lane) {
    unsigned mask = __ballot_sync(0xFFFFFFFFu, push);
    if (mask) {
        int leader = __ffs(mask) - 1;
        int base = 0;
        if (lane == leader) base = atomicAdd(&g_npre, __popc(mask));
        base = __shfl_sync(0xFFFFFFFFu, base, leader);
        if (push) {
            int pos = base + __popc(mask & ((1u << lane) - 1u));
            if (pos < PRE_CAP)
                g_pre[pos] = ((u64)(0x7FFFFFu - r) << 32) | (uint32_t)j;
        }
    }
}

// ---------------- K1: hash all slots, <=2 per thread, exactly 2 CTA waves ----------------
__global__ void __launch_bounds__(256)
k_hash_push(const int* __restrict__ d_size, int max_size, int data_len, int nsamp) {
    int new_size = read_scalar(d_size, max_size) + data_len;
    if (new_size > max_size) new_size = max_size;
    if (new_size < 0) new_size = 0;

    // keep top ~1.125*nsamp expected survivors (margin ~7.5 sigma)
    uint32_t precut = 0u;
    if (new_size > 0) {
        float keep_f = ((float)nsamp * 1.125f) * 8388608.0f / (float)new_size;
        u64 keep = (u64)keep_f;
        precut = (keep >= 0x800000ull) ? 0u : (uint32_t)(0x800000ull - keep);
    }

    const int lane = threadIdx.x & 31;
    const int j0 = blockIdx.x * 256 + threadIdx.x;
    const int j1 = j0 + HT;

    // two independent threefry chains (chain 1 dead for late blocks -> cheap wave 2)
    uint32_t r0 = 0u, r1 = 0u;
    bool p0 = false, p1 = false;
    if (j0 < new_size) { r0 = jax_bits32((uint32_t)j0) >> 9; p0 = (r0 >= precut); }
    if (j1 < new_size) { r1 = jax_bits32((uint32_t)j1) >> 9; p1 = (r1 >= precut); }
    warp_push(p0, r0, j0, lane);
    warp_push(p1, r1, j1, lane);
}

// ---------------- K2: tiled exact rank + counter snapshot ----------------
__global__ void k_rank() {
    int npre = g_npre;
    if (npre > PRE_CAP) npre = PRE_CAP;

    if (blockIdx.x == 0 && blockIdx.y == 0 && threadIdx.x == 0)
        g_npre2 = npre;   // snapshot for K3; K2->K3 stream ordering

    if ((int)(blockIdx.x * blockDim.x) >= npre) return;   // uniform per block

    __shared__ u64 sk[JCH];
    int chunk = (npre + JT - 1) / JT;
    int j0 = blockIdx.y * chunk;
    int j1 = j0 + chunk; if (j1 > npre) j1 = npre;
    if (j0 >= npre) return;
    for (int j = j0 + threadIdx.x; j < j1; j += blockDim.x)
        sk[j - j0] = g_pre[j];
    __syncthreads();

    int t = blockIdx.x * blockDim.x + threadIdx.x;
    u64 mykey = (t < npre) ? g_pre[t] : ~0ull;
    int len = j1 - j0;
    int cnt = 0, j = 0;
    for (; j + 4 <= len; j += 4) {
        cnt += (sk[j]     < mykey);
        cnt += (sk[j + 1] < mykey);
        cnt += (sk[j + 2] < mykey);
        cnt += (sk[j + 3] < mykey);
    }
    for (; j < len; ++j) cnt += (sk[j] < mykey);
    if (t < npre) g_rankp[blockIdx.y][t] = cnt;
}

// ---------------- K3: fused finalize + gather, warp per candidate ----------------
__global__ void __launch_bounds__(256)
k_rank_gather(const float* __restrict__ buf, const float* __restrict__ tr,
              const int* __restrict__ d_ins, float* __restrict__ out,
              int max_size, int data_len, int nsamp) {
    // reset K1's counter for the next run/replay; no thread here reads g_npre
    if (blockIdx.x == 0 && threadIdx.x == 0) g_npre = 0;

    int npre = g_npre2;
    if (npre > PRE_CAP) npre = PRE_CAP;

    const int lane   = threadIdx.x & 31;
    const int warp   = (blockIdx.x * blockDim.x + threadIdx.x) >> 5;
    const int nwarps = (gridDim.x * blockDim.x) >> 5;
    const long p_ins = (long)(read_scalar(d_ins, DEF_INSERT) % max_size);

    for (int t = warp; t < npre; t += nwarps) {
        // lanes 0..15 fetch the 16 rank partials in parallel
        int part = (lane < JT) ? g_rankp[lane][t] : 0;
        int rank = __reduce_add_sync(0xFFFFFFFFu, part);
        if (rank >= nsamp) continue;

        uint32_t idx = (uint32_t)g_pre[t];          // broadcast load
        long off = (long)idx - p_ins;
        if (off < 0) off += max_size;
        const float4* src = (off < (long)data_len)
            ? (const float4*)(tr + (size_t)off * FEAT)
            : (const float4*)(buf + (size_t)idx * FEAT);
        float4* dst = (float4*)(out + (size_t)rank * FEAT);

        float4 v0 = src[lane];                      // two independent loads
        float4 v1 = src[lane + 32];
        dst[lane]      = v0;
        dst[lane + 32] = v1;
    }
}

// ---------------- launcher ----------------
extern "C" void kernel_launch(void* const* d_in, const int* in_sizes, int n_in,
                              void* d_out, int out_size) {
    // Classify inputs by element count (robust to ordering):
    int i_buf = -1, i_tr = -1;
    int sc[3] = { -1, -1, -1 };
    int nsc = 0;
    for (int i = 0; i < n_in; ++i) {
        if (in_sizes[i] > 100000000)      i_buf = i;
        else if (in_sizes[i] > 1000000)   i_tr  = i;
        else if (in_sizes[i] >= 1 && in_sizes[i] <= 4 && nsc < 3) sc[nsc++] = i;
    }
    if (i_buf < 0) i_buf = 0;
    if (i_tr  < 0) i_tr  = 1;

    const float* buf   = (const float*)d_in[i_buf];
    const float* tr    = (const float*)d_in[i_tr];
    const int*   d_ins = (sc[0] >= 0) ? (const int*)d_in[sc[0]] : nullptr;
    const int*   d_sz  = (sc[1] >= 0) ? (const int*)d_in[sc[1]] : nullptr;

    int max_size = in_sizes[i_buf] / FEAT;   // 1,000,000
    int data_len = in_sizes[i_tr]  / FEAT;   // 16,384
    int nsamp    = out_size        / FEAT;   // 4,096

    k_hash_push<<<HB, 256>>>(d_sz, max_size, data_len, nsamp);
    dim3 rgrid(PRE_CAP / 256, JT);           // (64, 16)
    k_rank<<<rgrid, 256>>>();
    k_rank_gather<<<768, 256>>>(buf, tr, d_ins, (float*)d_out,
                                max_size, data_len, nsamp);   // 6144 warps
}

// round 16
// speedup vs baseline: 1.1009x; 1.0153x over previous
#include <cuda_runtime.h>
#include <cstdint>

#define FEAT      256
#define PRE_CAP   16384
#define JT        16
#define JCH       (PRE_CAP / JT)
#define DEF_INSERT 999000
#define HB        2368                // hash blocks: 2 CTA waves
#define HT        (HB * 256)

typedef unsigned long long u64;

// ---------------- device scratch (no allocations allowed; zero-init) ----------------
__device__ u64      g_pre[PRE_CAP];        // ((0x7FFFFF - r) << 32) | index
__device__ int      g_npre;                // K1 atomic counter; reset by K3 (never read there)
__device__ int      g_npre2;               // snapshot written by K2, read by K3
__device__ int      g_rankp[PRE_CAP][JT];  // TRANSPOSED: one 64B line per candidate

// ---------------- Threefry-2x32, 20 rounds, partitionable layout (JAX-exact) ----------------
__device__ __forceinline__ uint32_t rotl32(uint32_t x, int d) {
    return __funnelshift_l(x, x, d);
}

__device__ __forceinline__ uint32_t jax_bits32(uint32_t j) {
    const uint32_t k0 = 0u, k1 = 42u;
    const uint32_t ks2 = k0 ^ k1 ^ 0x1BD11BDAu;
    uint32_t x0 = 0u + k0, x1 = j + k1;
#define TF_R(r) { x0 += x1; x1 = rotl32(x1, (r)); x1 ^= x0; }
    TF_R(13) TF_R(15) TF_R(26) TF_R(6)   x0 += k1;  x1 += ks2 + 1u;
    TF_R(17) TF_R(29) TF_R(16) TF_R(24)  x0 += ks2; x1 += k0  + 2u;
    TF_R(13) TF_R(15) TF_R(26) TF_R(6)   x0 += k0;  x1 += k1  + 3u;
    TF_R(17) TF_R(29) TF_R(16) TF_R(24)  x0 += k1;  x1 += ks2 + 4u;
    TF_R(13) TF_R(15) TF_R(26) TF_R(6)   x0 += ks2; x1 += k0  + 5u;
#undef TF_R
    return x0 ^ x1;   // XOR-fold (jax_threefry_partitionable)
}

__device__ __forceinline__ int read_scalar(const int* p, int defv) {
    return p ? p[0] : defv;
}

__device__ __forceinline__ void warp_push(bool push, uint32_t bits, int j, int lane) {
    unsigned mask = __ballot_sync(0xFFFFFFFFu, push);
    if (mask) {
        int leader = __ffs(mask) - 1;
        int base = 0;
        if (lane == leader) base = atomicAdd(&g_npre, __popc(mask));
        base = __shfl_sync(0xFFFFFFFFu, base, leader);
        if (push) {
            int pos = base + __popc(mask & ((1u << lane) - 1u));
            if (pos < PRE_CAP) {
                uint32_t r = bits >> 9;   // 23-bit mantissa (rare path)
                g_pre[pos] = ((u64)(0x7FFFFFu - r) << 32) | (uint32_t)j;
            }
        }
    }
}

// ---------------- K1: hash all slots, <=2 per thread ----------------
__global__ void __launch_bounds__(256)
k_hash_push(const int* __restrict__ d_size, int max_size, int data_len, int nsamp) {
    int new_size = read_scalar(d_size, max_size) + data_len;
    if (new_size > max_size) new_size = max_size;
    if (new_size < 0) new_size = 0;

    // keep top ~1.125*nsamp expected survivors (margin ~7.5 sigma);
    // threshold applied to raw 32-bit bits (same survivor set as r >= precut)
    uint32_t precut_bits = 0u;
    if (new_size > 0) {
        float keep_f = ((float)nsamp * 1.125f) * 8388608.0f / (float)new_size;
        u64 keep = (u64)keep_f;
        uint32_t precut = (keep >= 0x800000ull) ? 0u : (uint32_t)(0x800000ull - keep);
        precut_bits = precut << 9;
    }

    const int lane = threadIdx.x & 31;
    const int j0 = blockIdx.x * 256 + threadIdx.x;
    const int j1 = j0 + HT;

    uint32_t b0 = 0u, b1 = 0u;
    bool p0 = false, p1 = false;
    if (j0 < new_size) { b0 = jax_bits32((uint32_t)j0); p0 = (b0 >= precut_bits); }
    if (j1 < new_size) { b1 = jax_bits32((uint32_t)j1); p1 = (b1 >= precut_bits); }
    warp_push(p0, b0, j0, lane);
    warp_push(p1, b1, j1, lane);
}

// ---------------- K2: tiled exact rank (transposed partial store) + snapshot ----------------
__global__ void k_rank() {
    int npre = g_npre;
    if (npre > PRE_CAP) npre = PRE_CAP;

    if (blockIdx.x == 0 && blockIdx.y == 0 && threadIdx.x == 0)
        g_npre2 = npre;   // snapshot for K3; K2->K3 stream ordering

    if ((int)(blockIdx.x * blockDim.x) >= npre) return;   // uniform per block

    __shared__ u64 sk[JCH];
    int chunk = (npre + JT - 1) / JT;
    int j0 = blockIdx.y * chunk;
    int j1 = j0 + chunk; if (j1 > npre) j1 = npre;
    if (j0 >= npre) return;   // empty tile: entry stays 0/stale-correct across replays
    for (int j = j0 + threadIdx.x; j < j1; j += blockDim.x)
        sk[j - j0] = g_pre[j];
    __syncthreads();

    int t = blockIdx.x * blockDim.x + threadIdx.x;
    u64 mykey = (t < npre) ? g_pre[t] : ~0ull;
    int len = j1 - j0;
    int cnt = 0, j = 0;
    for (; j + 4 <= len; j += 4) {
        cnt += (sk[j]     < mykey);
        cnt += (sk[j + 1] < mykey);
        cnt += (sk[j + 2] < mykey);
        cnt += (sk[j + 3] < mykey);
    }
    for (; j < len; ++j) cnt += (sk[j] < mykey);
    if (t < npre) g_rankp[t][blockIdx.y] = cnt;   // scattered store, off critical path
}

// ---------------- K3: fused finalize + gather, warp per candidate ----------------
__global__ void __launch_bounds__(256)
k_rank_gather(const float* __restrict__ buf, const float* __restrict__ tr,
              const int* __restrict__ d_ins, float* __restrict__ out,
              int max_size, int data_len, int nsamp) {
    // reset K1's counter for the next run/replay; no thread here reads g_npre
    if (blockIdx.x == 0 && threadIdx.x == 0) g_npre = 0;

    int npre = g_npre2;
    if (npre > PRE_CAP) npre = PRE_CAP;

    const int lane   = threadIdx.x & 31;
    const int warp   = (blockIdx.x * blockDim.x + threadIdx.x) >> 5;
    const int nwarps = (gridDim.x * blockDim.x) >> 5;
    const long p_ins = (long)(read_scalar(d_ins, DEF_INSERT) % max_size);

    for (int t = warp; t < npre; t += nwarps) {
        // both loads issued before the reduction (independent):
        // partials: one contiguous 64B line; key: broadcast
        int part = (lane < JT) ? g_rankp[t][lane] : 0;
        u64 key  = g_pre[t];
        int rank = __reduce_add_sync(0xFFFFFFFFu, part);
        if (rank >= nsamp) continue;

        uint32_t idx = (uint32_t)key;
        long off = (long)idx - p_ins;
        if (off < 0) off += max_size;
        const float4* src = (off < (long)data_len)
            ? (const float4*)(tr + (size_t)off * FEAT)
            : (const float4*)(buf + (size_t)idx * FEAT);
        float4* dst = (float4*)(out + (size_t)rank * FEAT);

        float4 v0 = src[lane];                      // two independent loads
        float4 v1 = src[lane + 32];
        dst[lane]      = v0;
        dst[lane + 32] = v1;
    }
}

// ---------------- launcher ----------------
extern "C" void kernel_launch(void* const* d_in, const int* in_sizes, int n_in,
                              void* d_out, int out_size) {
    // Classify inputs by element count (robust to ordering):
    int i_buf = -1, i_tr = -1;
    int sc[3] = { -1, -1, -1 };
    int nsc = 0;
    for (int i = 0; i < n_in; ++i) {
        if (in_sizes[i] > 100000000)      i_buf = i;
        else if (in_sizes[i] > 1000000)   i_tr  = i;
        else if (in_sizes[i] >= 1 && in_sizes[i] <= 4 && nsc < 3) sc[nsc++] = i;
    }
    if (i_buf < 0) i_buf = 0;
    if (i_tr  < 0) i_tr  = 1;

    const float* buf   = (const float*)d_in[i_buf];
    const float* tr    = (const float*)d_in[i_tr];
    const int*   d_ins = (sc[0] >= 0) ? (const int*)d_in[sc[0]] : nullptr;
    const int*   d_sz  = (sc[1] >= 0) ? (const int*)d_in[sc[1]] : nullptr;

    int max_size = in_sizes[i_buf] / FEAT;   // 1,000,000
    int data_len = in_sizes[i_tr]  / FEAT;   // 16,384
    int nsamp    = out_size        / FEAT;   // 4,096

    k_hash_push<<<HB, 256>>>(d_sz, max_size, data_len, nsamp);
    dim3 rgrid(PRE_CAP / 256, JT);           // (64, 16)
    k_rank<<<rgrid, 256>>>();
    k_rank_gather<<<768, 256>>>(buf, tr, d_ins, (float*)d_out,
                                max_size, data_len, nsamp);   // 6144 warps
}